// round 2
// baseline (speedup 1.0000x reference)
#include <cuda_runtime.h>
#include <cuda_bf16.h>
#include <cstdint>

// ---------------------------------------------------------------------------
// MLA forward, fp32 SIMT baseline.
//   B=2, S=2048, D=2048, H=16, DH=128, DL=512
// Pipeline (7 launches, all on default stream, graph-capturable):
//   1) z   = x @ w_latent + b_latent            [4096, 512]
//   2) q   = x @ w_q + b_q                      [4096, 2048]  (layout [B,S,H,DH])
//   3) k,v = z @ w_k[h] + b_k[h] (32 batches)   [H, 4096, 128]
//   4) scr = q @ k^T * 1/sqrt(DH)  (32 batches) [B*H, 2048, 2048]
//   5) softmax rows of scr
//   6) ao  = scr @ v (32 batches)               [B,S,H,DH] layout
//   7) out = ao @ w_o + b_o                     [4096, 2048]
// ---------------------------------------------------------------------------

#define BDIM 2
#define SEQ 2048
#define DMODEL 2048
#define NHEAD 16
#define DHEAD 128
#define DLAT 512
#define ROWS (BDIM * SEQ)          // 4096

// scratch (static device allocations; no cudaMalloc allowed)
__device__ float g_z[(size_t)ROWS * DLAT];                      //   8 MB
__device__ float g_q[(size_t)ROWS * DMODEL];                    //  32 MB
__device__ float g_k[(size_t)NHEAD * ROWS * DHEAD];             //  32 MB
__device__ float g_v[(size_t)NHEAD * ROWS * DHEAD];             //  32 MB
__device__ float g_scores[(size_t)BDIM * NHEAD * SEQ * SEQ];    // 512 MB
__device__ float g_ao[(size_t)ROWS * DMODEL];                   //  32 MB

// ---------------------------------------------------------------------------
// Generic register-tiled GEMM core: C = alpha * A@B (+ bias)
//   A: [M, K] row-major, leading dim lda
//   B: TRANSB ? [N, K] (ldb = row stride) : [K, N] (ldb = row stride)
//   C: [M, N], leading dim ldc
// Tile: 128x128, BK=8, 256 threads, 8x8 per thread.
// All problem dims here are multiples of the tile dims -> no bounds checks.
// ---------------------------------------------------------------------------
#define BM 128
#define BN 128
#define BK 8
#define TM 8
#define TN 8

template <bool TRANSB>
__device__ __forceinline__ void gemm_block(
    const float* __restrict__ A, int lda,
    const float* __restrict__ B, int ldb,
    const float* __restrict__ bias,
    float* __restrict__ C, int ldc,
    int K, float alpha)
{
    __shared__ float As[BK][BM];
    __shared__ float Bs[BK][BN];

    const int tid = threadIdx.x;
    const int m0 = blockIdx.y * BM;
    const int n0 = blockIdx.x * BN;

    // A-tile (and trans-B-tile) loader mapping: 128 rows x 8 cols, float4
    const int arow = tid >> 1;           // 0..127
    const int acol = (tid & 1) * 4;      // 0 or 4
    // non-trans B-tile loader mapping: 8 rows x 128 cols, float4
    const int brow = tid >> 5;           // 0..7
    const int bcol = (tid & 31) * 4;     // 0..124

    const int ty = tid >> 4;             // 0..15 (m direction)
    const int tx = tid & 15;             // 0..15 (n direction)

    float acc[TM][TN];
    #pragma unroll
    for (int i = 0; i < TM; i++)
        #pragma unroll
        for (int j = 0; j < TN; j++) acc[i][j] = 0.0f;

    for (int k0 = 0; k0 < K; k0 += BK) {
        // load A tile, transposed into As[k][m]
        {
            const float4 av = *reinterpret_cast<const float4*>(
                &A[(size_t)(m0 + arow) * lda + (k0 + acol)]);
            As[acol + 0][arow] = av.x;
            As[acol + 1][arow] = av.y;
            As[acol + 2][arow] = av.z;
            As[acol + 3][arow] = av.w;
        }
        // load B tile into Bs[k][n]
        if (TRANSB) {
            const float4 bv = *reinterpret_cast<const float4*>(
                &B[(size_t)(n0 + arow) * ldb + (k0 + acol)]);
            Bs[acol + 0][arow] = bv.x;
            Bs[acol + 1][arow] = bv.y;
            Bs[acol + 2][arow] = bv.z;
            Bs[acol + 3][arow] = bv.w;
        } else {
            const float4 bv = *reinterpret_cast<const float4*>(
                &B[(size_t)(k0 + brow) * ldb + (n0 + bcol)]);
            *reinterpret_cast<float4*>(&Bs[brow][bcol]) = bv;
        }
        __syncthreads();

        #pragma unroll
        for (int k = 0; k < BK; k++) {
            float ra[TM], rb[TN];
            #pragma unroll
            for (int i = 0; i < TM; i += 4) {
                const float4 v = *reinterpret_cast<const float4*>(&As[k][ty * TM + i]);
                ra[i] = v.x; ra[i + 1] = v.y; ra[i + 2] = v.z; ra[i + 3] = v.w;
            }
            #pragma unroll
            for (int j = 0; j < TN; j += 4) {
                const float4 v = *reinterpret_cast<const float4*>(&Bs[k][tx * TN + j]);
                rb[j] = v.x; rb[j + 1] = v.y; rb[j + 2] = v.z; rb[j + 3] = v.w;
            }
            #pragma unroll
            for (int i = 0; i < TM; i++)
                #pragma unroll
                for (int j = 0; j < TN; j++)
                    acc[i][j] = fmaf(ra[i], rb[j], acc[i][j]);
        }
        __syncthreads();
    }

    // epilogue
    #pragma unroll
    for (int i = 0; i < TM; i++) {
        const int m = m0 + ty * TM + i;
        #pragma unroll
        for (int j = 0; j < TN; j += 4) {
            const int n = n0 + tx * TN + j;
            float4 o;
            o.x = acc[i][j + 0] * alpha;
            o.y = acc[i][j + 1] * alpha;
            o.z = acc[i][j + 2] * alpha;
            o.w = acc[i][j + 3] * alpha;
            if (bias) {
                o.x += bias[n + 0];
                o.y += bias[n + 1];
                o.z += bias[n + 2];
                o.w += bias[n + 3];
            }
            *reinterpret_cast<float4*>(&C[(size_t)m * ldc + n]) = o;
        }
    }
}

// ------------------------- wrappers -------------------------

__global__ __launch_bounds__(256, 2)
void k_proj_z(const float* __restrict__ x, const float* __restrict__ w,
              const float* __restrict__ b)
{
    gemm_block<false>(x, DMODEL, w, DLAT, b, g_z, DLAT, DMODEL, 1.0f);
}

__global__ __launch_bounds__(256, 2)
void k_proj_q(const float* __restrict__ x, const float* __restrict__ w,
              const float* __restrict__ b)
{
    gemm_block<false>(x, DMODEL, w, DMODEL, b, g_q, DMODEL, DMODEL, 1.0f);
}

// blockIdx.z in [0, 32): low 4 bits = head, bit 4 = v (else k)
__global__ __launch_bounds__(256, 2)
void k_proj_kv(const float* __restrict__ wk, const float* __restrict__ bk,
               const float* __restrict__ wv, const float* __restrict__ bv)
{
    const int zb = blockIdx.z;
    const int h = zb & (NHEAD - 1);
    const bool isv = zb >= NHEAD;
    const float* w = (isv ? wv : wk) + (size_t)h * DLAT * DHEAD;
    const float* bb = (isv ? bv : bk) + (size_t)h * DHEAD;
    float* C = (isv ? g_v : g_k) + (size_t)h * ROWS * DHEAD;
    gemm_block<false>(g_z, DLAT, w, DHEAD, bb, C, DHEAD, DLAT, 1.0f);
}

// blockIdx.z in [0, 32): b = z>>4, h = z&15.  scores = q @ k^T / sqrt(DH)
__global__ __launch_bounds__(256, 2)
void k_scores()
{
    const int zb = blockIdx.z;
    const int b = zb >> 4;
    const int h = zb & (NHEAD - 1);
    const float* A = g_q + (size_t)b * SEQ * DMODEL + (size_t)h * DHEAD;
    const float* Bm = g_k + (size_t)h * ROWS * DHEAD + (size_t)b * SEQ * DHEAD;
    float* C = g_scores + (size_t)zb * SEQ * SEQ;
    gemm_block<true>(A, DMODEL, Bm, DHEAD, nullptr, C, SEQ, DHEAD,
                     0.08838834764831845f /* 1/sqrt(128) */);
}

__global__ __launch_bounds__(256, 2)
void k_attn_v()
{
    const int zb = blockIdx.z;
    const int b = zb >> 4;
    const int h = zb & (NHEAD - 1);
    const float* A = g_scores + (size_t)zb * SEQ * SEQ;
    const float* Bm = g_v + (size_t)h * ROWS * DHEAD + (size_t)b * SEQ * DHEAD;
    float* C = g_ao + (size_t)b * SEQ * DMODEL + (size_t)h * DHEAD;
    gemm_block<false>(A, SEQ, Bm, DHEAD, nullptr, C, DMODEL, SEQ, 1.0f);
}

__global__ __launch_bounds__(256, 2)
void k_proj_out(const float* __restrict__ w, const float* __restrict__ b,
                float* __restrict__ out)
{
    gemm_block<false>(g_ao, DMODEL, w, DMODEL, b, out, DMODEL, DMODEL, 1.0f);
}

// ------------------------- softmax -------------------------
// one block (256 threads) per row of 2048; each thread owns 8 contiguous vals
__global__ __launch_bounds__(256)
void k_softmax()
{
    __shared__ float red[9];
    const size_t row = blockIdx.x;
    float* p = g_scores + row * (size_t)SEQ;
    const int t = threadIdx.x;

    float4* pv = reinterpret_cast<float4*>(p);
    float4 a = pv[t * 2];
    float4 c = pv[t * 2 + 1];

    float m = fmaxf(fmaxf(fmaxf(a.x, a.y), fmaxf(a.z, a.w)),
                    fmaxf(fmaxf(c.x, c.y), fmaxf(c.z, c.w)));
    #pragma unroll
    for (int o = 16; o; o >>= 1) m = fmaxf(m, __shfl_xor_sync(0xffffffffu, m, o));
    if ((t & 31) == 0) red[t >> 5] = m;
    __syncthreads();
    if (t < 32) {
        float v = (t < 8) ? red[t] : -3.4e38f;
        #pragma unroll
        for (int o = 4; o; o >>= 1) v = fmaxf(v, __shfl_xor_sync(0xffffffffu, v, o));
        if (t == 0) red[8] = v;
    }
    __syncthreads();
    m = red[8];

    a.x = __expf(a.x - m); a.y = __expf(a.y - m);
    a.z = __expf(a.z - m); a.w = __expf(a.w - m);
    c.x = __expf(c.x - m); c.y = __expf(c.y - m);
    c.z = __expf(c.z - m); c.w = __expf(c.w - m);

    float s = (a.x + a.y + a.z + a.w) + (c.x + c.y + c.z + c.w);
    #pragma unroll
    for (int o = 16; o; o >>= 1) s += __shfl_xor_sync(0xffffffffu, s, o);
    __syncthreads();   // protect red[] reuse
    if ((t & 31) == 0) red[t >> 5] = s;
    __syncthreads();
    if (t < 32) {
        float v = (t < 8) ? red[t] : 0.0f;
        #pragma unroll
        for (int o = 4; o; o >>= 1) v += __shfl_xor_sync(0xffffffffu, v, o);
        if (t == 0) red[8] = v;
    }
    __syncthreads();
    const float inv = 1.0f / red[8];

    a.x *= inv; a.y *= inv; a.z *= inv; a.w *= inv;
    c.x *= inv; c.y *= inv; c.z *= inv; c.w *= inv;
    pv[t * 2] = a;
    pv[t * 2 + 1] = c;
}

// ------------------------- launch -------------------------

extern "C" void kernel_launch(void* const* d_in, const int* in_sizes, int n_in,
                              void* d_out, int out_size)
{
    const float* x        = (const float*)d_in[0];
    const float* w_latent = (const float*)d_in[1];
    const float* b_latent = (const float*)d_in[2];
    const float* w_q      = (const float*)d_in[3];
    const float* b_q      = (const float*)d_in[4];
    const float* w_k      = (const float*)d_in[5];
    const float* b_k      = (const float*)d_in[6];
    const float* w_v      = (const float*)d_in[7];
    const float* b_v      = (const float*)d_in[8];
    const float* w_o      = (const float*)d_in[9];
    const float* b_o      = (const float*)d_in[10];
    float* out            = (float*)d_out;

    dim3 blk(256);

    // 1) z = x @ w_latent + b_latent
    k_proj_z<<<dim3(DLAT / BN, ROWS / BM), blk>>>(x, w_latent, b_latent);
    // 2) q = x @ w_q + b_q
    k_proj_q<<<dim3(DMODEL / BN, ROWS / BM), blk>>>(x, w_q, b_q);
    // 3) k, v per head (32 batches: 16 k + 16 v)
    k_proj_kv<<<dim3(DHEAD / BN, ROWS / BM, 2 * NHEAD), blk>>>(w_k, b_k, w_v, b_v);
    // 4) scores = q @ k^T / sqrt(dh)
    k_scores<<<dim3(SEQ / BN, SEQ / BM, BDIM * NHEAD), blk>>>();
    // 5) softmax rows
    k_softmax<<<dim3(BDIM * NHEAD * SEQ), blk>>>();
    // 6) ao = scores @ v
    k_attn_v<<<dim3(DHEAD / BN, SEQ / BM, BDIM * NHEAD), blk>>>();
    // 7) out = ao @ w_o + b_o
    k_proj_out<<<dim3(DMODEL / BN, ROWS / BM), blk>>>(w_o, b_o, out);
}

// round 3
// speedup vs baseline: 2.7452x; 2.7452x over previous
#include <cuda_runtime.h>
#include <cuda_bf16.h>
#include <cstdint>

// ---------------------------------------------------------------------------
// MLA forward. tf32 tensor-core GEMM core (mma.sync m16n8k8), fp32 accumulate.
//   B=2, S=2048, D=2048, H=16, DH=128, DL=512
// 7 launches: z-proj, q-proj, kv-proj(32 batch), scores(32), softmax,
//             attn@v(32), out-proj.
// ---------------------------------------------------------------------------

#define BDIM 2
#define SEQ 2048
#define DMODEL 2048
#define NHEAD 16
#define DHEAD 128
#define DLAT 512
#define ROWS (BDIM * SEQ)          // 4096

__device__ float g_z[(size_t)ROWS * DLAT];
__device__ float g_q[(size_t)ROWS * DMODEL];
__device__ float g_k[(size_t)NHEAD * ROWS * DHEAD];
__device__ float g_v[(size_t)NHEAD * ROWS * DHEAD];
__device__ float g_scores[(size_t)BDIM * NHEAD * SEQ * SEQ];   // 512 MB
__device__ float g_ao[(size_t)ROWS * DMODEL];

#define BM 128
#define BN 128
#define BKT 16              // K per smem chunk (two k8 MMA steps)

__device__ __forceinline__ float4 cvt_tf32_4(float4 v)
{
    uint32_t x, y, z, w;
    asm("cvt.rna.tf32.f32 %0, %1;" : "=r"(x) : "f"(v.x));
    asm("cvt.rna.tf32.f32 %0, %1;" : "=r"(y) : "f"(v.y));
    asm("cvt.rna.tf32.f32 %0, %1;" : "=r"(z) : "f"(v.z));
    asm("cvt.rna.tf32.f32 %0, %1;" : "=r"(w) : "f"(v.w));
    float4 r;
    r.x = __uint_as_float(x); r.y = __uint_as_float(y);
    r.z = __uint_as_float(z); r.w = __uint_as_float(w);
    return r;
}

// C = alpha * A @ B (+bias).  A:[M,K] lda.  B: TRANSB ? [N,K] : [K,N], ldb.
// Tile 128x128, 256 threads (8 warps as 2x4), warp tile 64x32, tf32 MMA.
template <bool TRANSB>
__device__ __forceinline__ void gemm_tc(
    const float* __restrict__ A, int lda,
    const float* __restrict__ B, int ldb,
    const float* __restrict__ bias,
    float* __restrict__ C, int ldc,
    int K, float alpha)
{
    constexpr int ASTR = BKT + 4;       // 20 floats  (conflict-free frag reads)
    constexpr int BSTR_NN = BN + 8;     // 136 floats (conflict-free frag reads)
    constexpr int BS_SZ = TRANSB ? (BN * ASTR) : (BKT * BSTR_NN);

    __shared__ float As[2][BM * ASTR];
    __shared__ float Bs[2][BS_SZ];

    const int tid = threadIdx.x;
    const int lane = tid & 31;
    const int wid = tid >> 5;
    const int wm = wid & 1;             // warp row (0..1) -> 64 rows each
    const int wn = wid >> 1;            // warp col (0..3) -> 32 cols each
    const int grp = lane >> 2;          // 0..7
    const int qid = lane & 3;           // 0..3

    const int m0 = blockIdx.y * BM;
    const int n0 = blockIdx.x * BN;

    float4 pa[2], pb[2];

    // ---- global fetch of chunk k0 into registers ----
    auto fetch = [&](int k0) {
        #pragma unroll
        for (int p = 0; p < 2; p++) {
            const int id = tid + 256 * p;
            pa[p] = *reinterpret_cast<const float4*>(
                &A[(size_t)(m0 + (id >> 2)) * lda + k0 + (id & 3) * 4]);
            if (TRANSB) {
                pb[p] = *reinterpret_cast<const float4*>(
                    &B[(size_t)(n0 + (id >> 2)) * ldb + k0 + (id & 3) * 4]);
            } else {
                pb[p] = *reinterpret_cast<const float4*>(
                    &B[(size_t)(k0 + (id >> 5)) * ldb + n0 + (id & 31) * 4]);
            }
        }
    };

    // ---- convert to tf32 and store registers into smem buffer ----
    auto stage = [&](int buf) {
        #pragma unroll
        for (int p = 0; p < 2; p++) {
            const int id = tid + 256 * p;
            *reinterpret_cast<float4*>(
                &As[buf][(id >> 2) * ASTR + (id & 3) * 4]) = cvt_tf32_4(pa[p]);
            if (TRANSB) {
                *reinterpret_cast<float4*>(
                    &Bs[buf][(id >> 2) * ASTR + (id & 3) * 4]) = cvt_tf32_4(pb[p]);
            } else {
                *reinterpret_cast<float4*>(
                    &Bs[buf][(id >> 5) * BSTR_NN + (id & 31) * 4]) = cvt_tf32_4(pb[p]);
            }
        }
    };

    float acc[4][4][4];
    #pragma unroll
    for (int mi = 0; mi < 4; mi++)
        #pragma unroll
        for (int ni = 0; ni < 4; ni++)
            #pragma unroll
            for (int r = 0; r < 4; r++) acc[mi][ni][r] = 0.0f;

    auto compute = [&](int buf) {
        #pragma unroll
        for (int ks = 0; ks < BKT / 8; ks++) {
            uint32_t af[4][4];
            uint32_t bf[4][2];
            const int kc = ks * 8 + qid;
            #pragma unroll
            for (int mi = 0; mi < 4; mi++) {
                const int r = wm * 64 + mi * 16 + grp;
                af[mi][0] = __float_as_uint(As[buf][(r) * ASTR + kc]);
                af[mi][1] = __float_as_uint(As[buf][(r + 8) * ASTR + kc]);
                af[mi][2] = __float_as_uint(As[buf][(r) * ASTR + kc + 4]);
                af[mi][3] = __float_as_uint(As[buf][(r + 8) * ASTR + kc + 4]);
            }
            #pragma unroll
            for (int ni = 0; ni < 4; ni++) {
                const int n = wn * 32 + ni * 8 + grp;
                if (TRANSB) {
                    bf[ni][0] = __float_as_uint(Bs[buf][n * ASTR + kc]);
                    bf[ni][1] = __float_as_uint(Bs[buf][n * ASTR + kc + 4]);
                } else {
                    bf[ni][0] = __float_as_uint(Bs[buf][(kc) * BSTR_NN + n]);
                    bf[ni][1] = __float_as_uint(Bs[buf][(kc + 4) * BSTR_NN + n]);
                }
            }
            #pragma unroll
            for (int mi = 0; mi < 4; mi++)
                #pragma unroll
                for (int ni = 0; ni < 4; ni++) {
                    asm volatile(
                        "mma.sync.aligned.m16n8k8.row.col.f32.tf32.tf32.f32 "
                        "{%0,%1,%2,%3},{%4,%5,%6,%7},{%8,%9},{%0,%1,%2,%3};\n"
                        : "+f"(acc[mi][ni][0]), "+f"(acc[mi][ni][1]),
                          "+f"(acc[mi][ni][2]), "+f"(acc[mi][ni][3])
                        : "r"(af[mi][0]), "r"(af[mi][1]),
                          "r"(af[mi][2]), "r"(af[mi][3]),
                          "r"(bf[ni][0]), "r"(bf[ni][1]));
                }
        }
    };

    const int nchunk = K / BKT;
    fetch(0);
    stage(0);
    __syncthreads();

    for (int c = 0; c < nchunk; c++) {
        const int cur = c & 1;
        if (c + 1 < nchunk) fetch((c + 1) * BKT);
        compute(cur);
        if (c + 1 < nchunk) stage(cur ^ 1);
        __syncthreads();
    }

    // ---- epilogue ----
    const int row0 = m0 + wm * 64 + grp;
    const int col00 = n0 + wn * 32 + qid * 2;
    #pragma unroll
    for (int mi = 0; mi < 4; mi++) {
        #pragma unroll
        for (int ni = 0; ni < 4; ni++) {
            const int col = col00 + ni * 8;
            float bx = 0.0f, by = 0.0f;
            if (bias) { bx = bias[col]; by = bias[col + 1]; }
            const int r0 = row0 + mi * 16;
            float2 v0, v1;
            v0.x = acc[mi][ni][0] * alpha + bx;
            v0.y = acc[mi][ni][1] * alpha + by;
            v1.x = acc[mi][ni][2] * alpha + bx;
            v1.y = acc[mi][ni][3] * alpha + by;
            *reinterpret_cast<float2*>(&C[(size_t)r0 * ldc + col]) = v0;
            *reinterpret_cast<float2*>(&C[(size_t)(r0 + 8) * ldc + col]) = v1;
        }
    }
}

// ------------------------- wrappers -------------------------

__global__ __launch_bounds__(256)
void k_proj_z(const float* __restrict__ x, const float* __restrict__ w,
              const float* __restrict__ b)
{
    gemm_tc<false>(x, DMODEL, w, DLAT, b, g_z, DLAT, DMODEL, 1.0f);
}

__global__ __launch_bounds__(256)
void k_proj_q(const float* __restrict__ x, const float* __restrict__ w,
              const float* __restrict__ b)
{
    gemm_tc<false>(x, DMODEL, w, DMODEL, b, g_q, DMODEL, DMODEL, 1.0f);
}

__global__ __launch_bounds__(256)
void k_proj_kv(const float* __restrict__ wk, const float* __restrict__ bk,
               const float* __restrict__ wv, const float* __restrict__ bv)
{
    const int zb = blockIdx.z;
    const int h = zb & (NHEAD - 1);
    const bool isv = zb >= NHEAD;
    const float* w = (isv ? wv : wk) + (size_t)h * DLAT * DHEAD;
    const float* bb = (isv ? bv : bk) + (size_t)h * DHEAD;
    float* C = (isv ? g_v : g_k) + (size_t)h * ROWS * DHEAD;
    gemm_tc<false>(g_z, DLAT, w, DHEAD, bb, C, DHEAD, DLAT, 1.0f);
}

__global__ __launch_bounds__(256)
void k_scores()
{
    const int zb = blockIdx.z;
    const int b = zb >> 4;
    const int h = zb & (NHEAD - 1);
    const float* A = g_q + (size_t)b * SEQ * DMODEL + (size_t)h * DHEAD;
    const float* Bm = g_k + (size_t)h * ROWS * DHEAD + (size_t)b * SEQ * DHEAD;
    float* C = g_scores + (size_t)zb * SEQ * SEQ;
    gemm_tc<true>(A, DMODEL, Bm, DHEAD, nullptr, C, SEQ, DHEAD,
                  0.08838834764831845f /* 1/sqrt(128) */);
}

__global__ __launch_bounds__(256)
void k_attn_v()
{
    const int zb = blockIdx.z;
    const int b = zb >> 4;
    const int h = zb & (NHEAD - 1);
    const float* A = g_scores + (size_t)zb * SEQ * SEQ;
    const float* Bm = g_v + (size_t)h * ROWS * DHEAD + (size_t)b * SEQ * DHEAD;
    float* C = g_ao + (size_t)b * SEQ * DMODEL + (size_t)h * DHEAD;
    gemm_tc<false>(A, SEQ, Bm, DHEAD, nullptr, C, DMODEL, SEQ, 1.0f);
}

__global__ __launch_bounds__(256)
void k_proj_out(const float* __restrict__ w, const float* __restrict__ b,
                float* __restrict__ out)
{
    gemm_tc<false>(g_ao, DMODEL, w, DMODEL, b, out, DMODEL, DMODEL, 1.0f);
}

// ------------------------- softmax -------------------------
__global__ __launch_bounds__(256)
void k_softmax()
{
    __shared__ float red[9];
    const size_t row = blockIdx.x;
    float* p = g_scores + row * (size_t)SEQ;
    const int t = threadIdx.x;

    float4* pv = reinterpret_cast<float4*>(p);
    float4 a = pv[t * 2];
    float4 c = pv[t * 2 + 1];

    float m = fmaxf(fmaxf(fmaxf(a.x, a.y), fmaxf(a.z, a.w)),
                    fmaxf(fmaxf(c.x, c.y), fmaxf(c.z, c.w)));
    #pragma unroll
    for (int o = 16; o; o >>= 1) m = fmaxf(m, __shfl_xor_sync(0xffffffffu, m, o));
    if ((t & 31) == 0) red[t >> 5] = m;
    __syncthreads();
    if (t < 32) {
        float v = (t < 8) ? red[t] : -3.4e38f;
        #pragma unroll
        for (int o = 4; o; o >>= 1) v = fmaxf(v, __shfl_xor_sync(0xffffffffu, v, o));
        if (t == 0) red[8] = v;
    }
    __syncthreads();
    m = red[8];

    a.x = __expf(a.x - m); a.y = __expf(a.y - m);
    a.z = __expf(a.z - m); a.w = __expf(a.w - m);
    c.x = __expf(c.x - m); c.y = __expf(c.y - m);
    c.z = __expf(c.z - m); c.w = __expf(c.w - m);

    float s = (a.x + a.y + a.z + a.w) + (c.x + c.y + c.z + c.w);
    #pragma unroll
    for (int o = 16; o; o >>= 1) s += __shfl_xor_sync(0xffffffffu, s, o);
    __syncthreads();
    if ((t & 31) == 0) red[t >> 5] = s;
    __syncthreads();
    if (t < 32) {
        float v = (t < 8) ? red[t] : 0.0f;
        #pragma unroll
        for (int o = 4; o; o >>= 1) v += __shfl_xor_sync(0xffffffffu, v, o);
        if (t == 0) red[8] = v;
    }
    __syncthreads();
    const float inv = 1.0f / red[8];

    a.x *= inv; a.y *= inv; a.z *= inv; a.w *= inv;
    c.x *= inv; c.y *= inv; c.z *= inv; c.w *= inv;
    pv[t * 2] = a;
    pv[t * 2 + 1] = c;
}

// ------------------------- launch -------------------------

extern "C" void kernel_launch(void* const* d_in, const int* in_sizes, int n_in,
                              void* d_out, int out_size)
{
    const float* x        = (const float*)d_in[0];
    const float* w_latent = (const float*)d_in[1];
    const float* b_latent = (const float*)d_in[2];
    const float* w_q      = (const float*)d_in[3];
    const float* b_q      = (const float*)d_in[4];
    const float* w_k      = (const float*)d_in[5];
    const float* b_k      = (const float*)d_in[6];
    const float* w_v      = (const float*)d_in[7];
    const float* b_v      = (const float*)d_in[8];
    const float* w_o      = (const float*)d_in[9];
    const float* b_o      = (const float*)d_in[10];
    float* out            = (float*)d_out;

    dim3 blk(256);

    k_proj_z<<<dim3(DLAT / BN, ROWS / BM), blk>>>(x, w_latent, b_latent);
    k_proj_q<<<dim3(DMODEL / BN, ROWS / BM), blk>>>(x, w_q, b_q);
    k_proj_kv<<<dim3(DHEAD / BN, ROWS / BM, 2 * NHEAD), blk>>>(w_k, b_k, w_v, b_v);
    k_scores<<<dim3(SEQ / BN, SEQ / BM, BDIM * NHEAD), blk>>>();
    k_softmax<<<dim3(BDIM * NHEAD * SEQ), blk>>>();
    k_attn_v<<<dim3(DHEAD / BN, SEQ / BM, BDIM * NHEAD), blk>>>();
    k_proj_out<<<dim3(DMODEL / BN, ROWS / BM), blk>>>(w_o, b_o, out);
}

// round 8
// speedup vs baseline: 3.3463x; 1.2190x over previous
#include <cuda_runtime.h>
#include <cuda_bf16.h>
#include <cstdint>

// ---------------------------------------------------------------------------
// MLA forward. tf32 mma.sync GEMMs with cp.async 2-stage pipeline.
// All GEMM operands are pre-rounded to tf32 (stored in fp32 words), so the
// mainloop is pure LDGSTS + LDS + MMA.
//   B=2, S=2048, D=2048, H=16, DH=128, DL=512
// ---------------------------------------------------------------------------

#define BDIM 2
#define SEQ 2048
#define DMODEL 2048
#define NHEAD 16
#define DHEAD 128
#define DLAT 512
#define ROWS (BDIM * SEQ)          // 4096

// intermediates (producers write tf32-rounded values)
__device__ float g_z[(size_t)ROWS * DLAT];
__device__ float g_q[(size_t)ROWS * DMODEL];
__device__ float g_k[(size_t)NHEAD * ROWS * DHEAD];
__device__ float g_v[(size_t)NHEAD * ROWS * DHEAD];
__device__ float g_scores[(size_t)BDIM * NHEAD * SEQ * SEQ];   // 512 MB
__device__ float g_ao[(size_t)ROWS * DMODEL];

// tf32-rounded copies of harness inputs
__device__ float g_xc[(size_t)ROWS * DMODEL];
__device__ float g_wlat[(size_t)DMODEL * DLAT];
__device__ float g_wq[(size_t)DMODEL * DMODEL];
__device__ float g_wk[(size_t)NHEAD * DLAT * DHEAD];
__device__ float g_wv[(size_t)NHEAD * DLAT * DHEAD];
__device__ float g_wo[(size_t)DMODEL * DMODEL];

#define BM 128
#define BN 128
#define BKT 16

// ---------------- helpers ----------------

__device__ __forceinline__ float cvt_tf32(float v)
{
    uint32_t u;
    asm("cvt.rna.tf32.f32 %0, %1;" : "=r"(u) : "f"(v));
    return __uint_as_float(u);
}

__device__ __forceinline__ float4 cvt_tf32_4(float4 v)
{
    float4 r;
    r.x = cvt_tf32(v.x); r.y = cvt_tf32(v.y);
    r.z = cvt_tf32(v.z); r.w = cvt_tf32(v.w);
    return r;
}

__device__ __forceinline__ void cp_async16(void* smem_dst, const void* gmem_src)
{
    uint32_t s = (uint32_t)__cvta_generic_to_shared(smem_dst);
    asm volatile("cp.async.cg.shared.global [%0], [%1], 16;\n" :: "r"(s), "l"(gmem_src));
}
__device__ __forceinline__ void cp_commit()
{
    asm volatile("cp.async.commit_group;\n");
}
template <int N>
__device__ __forceinline__ void cp_wait()
{
    asm volatile("cp.async.wait_group %0;\n" :: "n"(N));
}

// ---------------- GEMM core ----------------
// C = alpha * A @ B (+bias).  A:[M,K] lda.  B: TRANSB ? [N,K] : [K,N], ldb.
// 128x128 tile, 256 thr (8 warps 2x4), warp tile 64x32, tf32 m16n8k8 MMA.
// Operands must already be tf32-rounded. If RND, output is tf32-rounded too.
template <bool TRANSB, bool RND>
__device__ __forceinline__ void gemm_tc(
    const float* __restrict__ A, int lda,
    const float* __restrict__ B, int ldb,
    const float* __restrict__ bias,
    float* __restrict__ C, int ldc,
    int K, float alpha)
{
    constexpr int ASTR = BKT + 4;       // 20 floats, conflict-free frag reads
    constexpr int BSTR_NN = BN + 8;     // 136 floats
    constexpr int BS_SZ = TRANSB ? (BN * ASTR) : (BKT * BSTR_NN);

    __shared__ float As[2][BM * ASTR];
    __shared__ float Bs[2][BS_SZ];

    const int tid = threadIdx.x;
    const int lane = tid & 31;
    const int wid = tid >> 5;
    const int wm = wid & 1;
    const int wn = wid >> 1;
    const int grp = lane >> 2;
    const int qid = lane & 3;

    const int m0 = blockIdx.y * BM;
    const int n0 = blockIdx.x * BN;

    // cp.async loaders: 512 x 16B chunks per tile pair, 2 per thread each
    auto issue = [&](int buf, int k0) {
        #pragma unroll
        for (int p = 0; p < 2; p++) {
            const int id = tid + 256 * p;
            // A: 128 rows x 4 chunks
            cp_async16(&As[buf][(id >> 2) * ASTR + (id & 3) * 4],
                       &A[(size_t)(m0 + (id >> 2)) * lda + k0 + (id & 3) * 4]);
            if (TRANSB) {
                cp_async16(&Bs[buf][(id >> 2) * ASTR + (id & 3) * 4],
                           &B[(size_t)(n0 + (id >> 2)) * ldb + k0 + (id & 3) * 4]);
            } else {
                cp_async16(&Bs[buf][(id >> 5) * BSTR_NN + (id & 31) * 4],
                           &B[(size_t)(k0 + (id >> 5)) * ldb + n0 + (id & 31) * 4]);
            }
        }
        cp_commit();
    };

    float acc[4][4][4];
    #pragma unroll
    for (int mi = 0; mi < 4; mi++)
        #pragma unroll
        for (int ni = 0; ni < 4; ni++)
            #pragma unroll
            for (int r = 0; r < 4; r++) acc[mi][ni][r] = 0.0f;

    auto compute = [&](int buf) {
        #pragma unroll
        for (int ks = 0; ks < BKT / 8; ks++) {
            uint32_t af[4][4];
            uint32_t bf[4][2];
            const int kc = ks * 8 + qid;
            #pragma unroll
            for (int mi = 0; mi < 4; mi++) {
                const int r = wm * 64 + mi * 16 + grp;
                af[mi][0] = __float_as_uint(As[buf][(r) * ASTR + kc]);
                af[mi][1] = __float_as_uint(As[buf][(r + 8) * ASTR + kc]);
                af[mi][2] = __float_as_uint(As[buf][(r) * ASTR + kc + 4]);
                af[mi][3] = __float_as_uint(As[buf][(r + 8) * ASTR + kc + 4]);
            }
            #pragma unroll
            for (int ni = 0; ni < 4; ni++) {
                const int n = wn * 32 + ni * 8 + grp;
                if (TRANSB) {
                    bf[ni][0] = __float_as_uint(Bs[buf][n * ASTR + kc]);
                    bf[ni][1] = __float_as_uint(Bs[buf][n * ASTR + kc + 4]);
                } else {
                    bf[ni][0] = __float_as_uint(Bs[buf][(kc) * BSTR_NN + n]);
                    bf[ni][1] = __float_as_uint(Bs[buf][(kc + 4) * BSTR_NN + n]);
                }
            }
            #pragma unroll
            for (int mi = 0; mi < 4; mi++)
                #pragma unroll
                for (int ni = 0; ni < 4; ni++) {
                    asm volatile(
                        "mma.sync.aligned.m16n8k8.row.col.f32.tf32.tf32.f32 "
                        "{%0,%1,%2,%3},{%4,%5,%6,%7},{%8,%9},{%0,%1,%2,%3};\n"
                        : "+f"(acc[mi][ni][0]), "+f"(acc[mi][ni][1]),
                          "+f"(acc[mi][ni][2]), "+f"(acc[mi][ni][3])
                        : "r"(af[mi][0]), "r"(af[mi][1]),
                          "r"(af[mi][2]), "r"(af[mi][3]),
                          "r"(bf[ni][0]), "r"(bf[ni][1]));
                }
        }
    };

    const int nchunk = K / BKT;
    issue(0, 0);
    for (int c = 0; c < nchunk; c++) {
        if (c + 1 < nchunk) {
            issue((c + 1) & 1, (c + 1) * BKT);
            cp_wait<1>();
        } else {
            cp_wait<0>();
        }
        __syncthreads();
        compute(c & 1);
        __syncthreads();   // buf (c&1) reusable at iteration c+1's issue
    }

    // ---- epilogue ----
    const int row0 = m0 + wm * 64 + grp;
    const int col00 = n0 + wn * 32 + qid * 2;
    #pragma unroll
    for (int mi = 0; mi < 4; mi++) {
        #pragma unroll
        for (int ni = 0; ni < 4; ni++) {
            const int col = col00 + ni * 8;
            float bx = 0.0f, by = 0.0f;
            if (bias) { bx = bias[col]; by = bias[col + 1]; }
            const int r0 = row0 + mi * 16;
            float2 v0, v1;
            v0.x = acc[mi][ni][0] * alpha + bx;
            v0.y = acc[mi][ni][1] * alpha + by;
            v1.x = acc[mi][ni][2] * alpha + bx;
            v1.y = acc[mi][ni][3] * alpha + by;
            if (RND) {
                v0.x = cvt_tf32(v0.x); v0.y = cvt_tf32(v0.y);
                v1.x = cvt_tf32(v1.x); v1.y = cvt_tf32(v1.y);
            }
            *reinterpret_cast<float2*>(&C[(size_t)r0 * ldc + col]) = v0;
            *reinterpret_cast<float2*>(&C[(size_t)(r0 + 8) * ldc + col]) = v1;
        }
    }
}

// ---------------- input rounding pre-pass ----------------
__global__ __launch_bounds__(256)
void k_cvt(const float* __restrict__ in, float* __restrict__ out, int n4)
{
    const int i = blockIdx.x * 256 + threadIdx.x;
    if (i < n4) {
        reinterpret_cast<float4*>(out)[i] =
            cvt_tf32_4(reinterpret_cast<const float4*>(in)[i]);
    }
}

// ---------------- GEMM wrappers ----------------

__global__ __launch_bounds__(256, 2)
void k_proj_z(const float* __restrict__ b)
{
    gemm_tc<false, true>(g_xc, DMODEL, g_wlat, DLAT, b, g_z, DLAT, DMODEL, 1.0f);
}

__global__ __launch_bounds__(256, 2)
void k_proj_q(const float* __restrict__ b)
{
    gemm_tc<false, true>(g_xc, DMODEL, g_wq, DMODEL, b, g_q, DMODEL, DMODEL, 1.0f);
}

__global__ __launch_bounds__(256, 2)
void k_proj_kv(const float* __restrict__ bk, const float* __restrict__ bv)
{
    const int zb = blockIdx.z;
    const int h = zb & (NHEAD - 1);
    const bool isv = zb >= NHEAD;
    const float* w = (isv ? g_wv : g_wk) + (size_t)h * DLAT * DHEAD;
    const float* bb = (isv ? bv : bk) + (size_t)h * DHEAD;
    float* C = (isv ? g_v : g_k) + (size_t)h * ROWS * DHEAD;
    gemm_tc<false, true>(g_z, DLAT, w, DHEAD, bb, C, DHEAD, DLAT, 1.0f);
}

__global__ __launch_bounds__(256, 2)
void k_scores()
{
    const int zb = blockIdx.z;
    const int b = zb >> 4;
    const int h = zb & (NHEAD - 1);
    const float* A = g_q + (size_t)b * SEQ * DMODEL + (size_t)h * DHEAD;
    const float* Bm = g_k + (size_t)h * ROWS * DHEAD + (size_t)b * SEQ * DHEAD;
    float* C = g_scores + (size_t)zb * SEQ * SEQ;
    gemm_tc<true, false>(A, DMODEL, Bm, DHEAD, nullptr, C, SEQ, DHEAD,
                         0.08838834764831845f /* 1/sqrt(128) */);
}

__global__ __launch_bounds__(256, 2)
void k_attn_v()
{
    const int zb = blockIdx.z;
    const int b = zb >> 4;
    const int h = zb & (NHEAD - 1);
    const float* A = g_scores + (size_t)zb * SEQ * SEQ;
    const float* Bm = g_v + (size_t)h * ROWS * DHEAD + (size_t)b * SEQ * DHEAD;
    float* C = g_ao + (size_t)b * SEQ * DMODEL + (size_t)h * DHEAD;
    gemm_tc<false, true>(A, SEQ, Bm, DHEAD, nullptr, C, DMODEL, SEQ, 1.0f);
}

__global__ __launch_bounds__(256, 2)
void k_proj_out(const float* __restrict__ b, float* __restrict__ out)
{
    gemm_tc<false, false>(g_ao, DMODEL, g_wo, DMODEL, b, out, DMODEL, DMODEL, 1.0f);
}

// ---------------- softmax (writes tf32-rounded probs) ----------------
__global__ __launch_bounds__(256)
void k_softmax()
{
    __shared__ float red[9];
    const size_t row = blockIdx.x;
    float* p = g_scores + row * (size_t)SEQ;
    const int t = threadIdx.x;

    float4* pv = reinterpret_cast<float4*>(p);
    float4 a = pv[t * 2];
    float4 c = pv[t * 2 + 1];

    float m = fmaxf(fmaxf(fmaxf(a.x, a.y), fmaxf(a.z, a.w)),
                    fmaxf(fmaxf(c.x, c.y), fmaxf(c.z, c.w)));
    #pragma unroll
    for (int o = 16; o; o >>= 1) m = fmaxf(m, __shfl_xor_sync(0xffffffffu, m, o));
    if ((t & 31) == 0) red[t >> 5] = m;
    __syncthreads();
    if (t < 32) {
        float v = (t < 8) ? red[t] : -3.4e38f;
        #pragma unroll
        for (int o = 4; o; o >>= 1) v = fmaxf(v, __shfl_xor_sync(0xffffffffu, v, o));
        if (t == 0) red[8] = v;
    }
    __syncthreads();
    m = red[8];

    a.x = __expf(a.x - m); a.y = __expf(a.y - m);
    a.z = __expf(a.z - m); a.w = __expf(a.w - m);
    c.x = __expf(c.x - m); c.y = __expf(c.y - m);
    c.z = __expf(c.z - m); c.w = __expf(c.w - m);

    float s = (a.x + a.y + a.z + a.w) + (c.x + c.y + c.z + c.w);
    #pragma unroll
    for (int o = 16; o; o >>= 1) s += __shfl_xor_sync(0xffffffffu, s, o);
    __syncthreads();
    if ((t & 31) == 0) red[t >> 5] = s;
    __syncthreads();
    if (t < 32) {
        float v = (t < 8) ? red[t] : 0.0f;
        #pragma unroll
        for (int o = 4; o; o >>= 1) v += __shfl_xor_sync(0xffffffffu, v, o);
        if (t == 0) red[8] = v;
    }
    __syncthreads();
    const float inv = 1.0f / red[8];

    a.x *= inv; a.y *= inv; a.z *= inv; a.w *= inv;
    c.x *= inv; c.y *= inv; c.z *= inv; c.w *= inv;
    pv[t * 2] = cvt_tf32_4(a);
    pv[t * 2 + 1] = cvt_tf32_4(c);
}

// ---------------- launch ----------------

extern "C" void kernel_launch(void* const* d_in, const int* in_sizes, int n_in,
                              void* d_out, int out_size)
{
    const float* x        = (const float*)d_in[0];
    const float* w_latent = (const float*)d_in[1];
    const float* b_latent = (const float*)d_in[2];
    const float* w_q      = (const float*)d_in[3];
    const float* b_q      = (const float*)d_in[4];
    const float* w_k      = (const float*)d_in[5];
    const float* b_k      = (const float*)d_in[6];
    const float* w_v      = (const float*)d_in[7];
    const float* b_v      = (const float*)d_in[8];
    const float* w_o      = (const float*)d_in[9];
    const float* b_o      = (const float*)d_in[10];
    float* out            = (float*)d_out;

    dim3 blk(256);

    // device-symbol addresses (host side)
    float *p_xc, *p_wlat, *p_wq, *p_wk, *p_wv, *p_wo;
    cudaGetSymbolAddress((void**)&p_xc,   g_xc);
    cudaGetSymbolAddress((void**)&p_wlat, g_wlat);
    cudaGetSymbolAddress((void**)&p_wq,   g_wq);
    cudaGetSymbolAddress((void**)&p_wk,   g_wk);
    cudaGetSymbolAddress((void**)&p_wv,   g_wv);
    cudaGetSymbolAddress((void**)&p_wo,   g_wo);

    auto cvt = [&](const float* src, float* dst, size_t n) {
        const int n4 = (int)(n / 4);
        k_cvt<<<(n4 + 255) / 256, blk>>>(src, dst, n4);
    };
    cvt(x,        p_xc,   (size_t)ROWS * DMODEL);
    cvt(w_latent, p_wlat, (size_t)DMODEL * DLAT);
    cvt(w_q,      p_wq,   (size_t)DMODEL * DMODEL);
    cvt(w_k,      p_wk,   (size_t)NHEAD * DLAT * DHEAD);
    cvt(w_v,      p_wv,   (size_t)NHEAD * DLAT * DHEAD);
    cvt(w_o,      p_wo,   (size_t)DMODEL * DMODEL);

    k_proj_z<<<dim3(DLAT / BN, ROWS / BM), blk>>>(b_latent);
    k_proj_q<<<dim3(DMODEL / BN, ROWS / BM), blk>>>(b_q);
    k_proj_kv<<<dim3(DHEAD / BN, ROWS / BM, 2 * NHEAD), blk>>>(b_k, b_v);
    k_scores<<<dim3(SEQ / BN, SEQ / BM, BDIM * NHEAD), blk>>>();
    k_softmax<<<dim3(BDIM * NHEAD * SEQ), blk>>>();
    k_attn_v<<<dim3(DHEAD / BN, SEQ / BM, BDIM * NHEAD), blk>>>();
    k_proj_out<<<dim3(DMODEL / BN, ROWS / BM), blk>>>(b_o, out);
}